// round 4
// baseline (speedup 1.0000x reference)
#include <cuda_runtime.h>
#include <math.h>

#define DIMX 512
#define CBD  14
#define CBS  16384
#define NTHR 256
#define TPB  32           // tokens per block-group
#define MAXBLK 128

typedef unsigned long long ull;

// Persistent device scratch (zero-initialized at load; tail re-zeros after use)
__device__ float g_avgp[CBS];
__device__ float g_scal[2];          // [0] entropy sum, [1] commit sum
__device__ float g_ent;              // codebook-entropy accumulator
__device__ unsigned int g_ctr;       // phase-A arrival counter
__device__ unsigned int g_ctr2;      // phase-B arrival counter

// ---- packed f32x2 helpers ----
__device__ __forceinline__ ull ffma2(ull a, ull b, ull c) {
    ull d; asm("fma.rn.f32x2 %0, %1, %2, %3;" : "=l"(d) : "l"(a), "l"(b), "l"(c)); return d;
}
__device__ __forceinline__ ull fadd2(ull a, ull b) {
    ull d; asm("add.rn.f32x2 %0, %1, %2;" : "=l"(d) : "l"(a), "l"(b)); return d;
}
__device__ __forceinline__ ull pack2(float lo, float hi) {
    ull r; asm("mov.b64 %0, {%1, %2};" : "=l"(r) : "f"(lo), "f"(hi)); return r;
}
__device__ __forceinline__ void unpack2(ull v, float& lo, float& hi) {
    asm("mov.b64 {%0, %1}, %2;" : "=f"(lo), "=f"(hi) : "l"(v));
}

// shared-memory layout (bytes)
#define O_X 0                 // 32 rows x 129 ull2 = 66048
#define O_W 66048             // w_in staged: 14*128 ull2 = 28672
#define O_P 94720             // partials: 8*14*32 ull = 28672
#define O_H 123392            // h: 448 floats = 1792
#define O_Q 125184            // q(+-1): 448 floats = 1792
#define SMEM_TOTAL 126976

__global__ void __launch_bounds__(NTHR, 1) lfq_main(
    const float* __restrict__ x,
    const float* __restrict__ w_in,
    const float* __restrict__ b_in,
    const float* __restrict__ w_out,
    const float* __restrict__ b_out,
    float* __restrict__ out,
    float* __restrict__ idxf,
    float* __restrict__ aux,
    int ntok)
{
    extern __shared__ unsigned char smem[];
    ulonglong2* sx  = (ulonglong2*)(smem + O_X);
    ulonglong2* swi = (ulonglong2*)(smem + O_W);
    ull*        sp  = (ull*)       (smem + O_P);
    float*      shh = (float*)     (smem + O_H);
    float*      shq = (float*)     (smem + O_Q);

    const int tid  = threadIdx.x;
    const int lane = tid & 31;
    const int wid  = tid >> 5;

    // stage w_in [14][512] into shared once (coalesced, 28KB)
    {
        const ulonglong2* wsrc = (const ulonglong2*)w_in;
#pragma unroll
        for (int i = 0; i < 7; i++) swi[i * 256 + tid] = wsrc[i * 256 + tid];
    }

    for (int base = blockIdx.x * TPB; base < ntok; base += gridDim.x * TPB) {
        __syncthreads();

        // ---- stage 32 token rows of x into padded shared (coalesced) ----
#pragma unroll
        for (int i = 0; i < 16; i++) {
            int idx = i * 256 + tid;
            int t = idx >> 7, c = idx & 127;
            ulonglong2 v;
            if (base + t < ntok) v = *(const ulonglong2*)(x + (size_t)(base + t) * DIMX + c * 4);
            else { v.x = 0ull; v.y = 0ull; }
            sx[t * 129 + c] = v;
        }
        __syncthreads();

        // ---- phase 1: h = x @ w_in^T  (lane = token, warp = 64-col chunk) ----
        ull acc[CBD];
#pragma unroll
        for (int d = 0; d < CBD; d++) acc[d] = 0ull;
        {
            const ulonglong2* xs = sx + lane * 129 + wid * 16;
            const ulonglong2* ws = swi + wid * 16;
#pragma unroll 4
            for (int j = 0; j < 16; j++) {
                ulonglong2 xv = xs[j];
#pragma unroll
                for (int d = 0; d < CBD; d++) {
                    ulonglong2 wv = ws[d * 128 + j];
                    acc[d] = ffma2(xv.x, wv.x, ffma2(xv.y, wv.y, acc[d]));
                }
            }
        }
#pragma unroll
        for (int d = 0; d < CBD; d++) sp[wid * 448 + d * 32 + lane] = acc[d];
        __syncthreads();

        // ---- cross-warp reduce (tree, packed), add b_in, compute sign ----
#pragma unroll
        for (int r = 0; r < 2; r++) {
            int p = tid + r * 256;
            if (p < 448) {
                ull s0 = fadd2(sp[0 * 448 + p], sp[1 * 448 + p]);
                ull s1 = fadd2(sp[2 * 448 + p], sp[3 * 448 + p]);
                ull s2 = fadd2(sp[4 * 448 + p], sp[5 * 448 + p]);
                ull s3 = fadd2(sp[6 * 448 + p], sp[7 * 448 + p]);
                ull s  = fadd2(fadd2(s0, s1), fadd2(s2, s3));
                float lo, hi; unpack2(s, lo, hi);
                float h = lo + hi + __ldg(b_in + (p >> 5));
                shh[p] = h;
                shq[p] = (h > 0.0f) ? 1.0f : -1.0f;
            }
        }
        __syncthreads();

        // ---- phase 2: out = q @ w_out^T, fused e-pair (e0=2tid, e1=2tid+1) ----
        {
            const int e0 = 2 * tid, e1 = 2 * tid + 1;
            float wo0[CBD], wo1[CBD];
            {   // 28 contiguous floats, 16B aligned (112*tid % 16 == 0)
                float4 tmp[7];
                const float4* wp = (const float4*)(w_out + (size_t)e0 * CBD);
#pragma unroll
                for (int i = 0; i < 7; i++) tmp[i] = wp[i];
                const float* tf = (const float*)tmp;
#pragma unroll
                for (int d = 0; d < CBD; d++) { wo0[d] = tf[d]; wo1[d] = tf[CBD + d]; }
            }
            ull a0[16], a1[16];
            {
                ull b0 = pack2(__ldg(b_out + e0), __ldg(b_out + e0));
                ull b1 = pack2(__ldg(b_out + e1), __ldg(b_out + e1));
#pragma unroll
                for (int tp = 0; tp < 16; tp++) { a0[tp] = b0; a1[tp] = b1; }
            }
#pragma unroll
            for (int d = 0; d < CBD; d++) {
                ull w0 = pack2(wo0[d], wo0[d]);
                ull w1 = pack2(wo1[d], wo1[d]);
                const ull* qrow = (const ull*)(shq + d * 32);
#pragma unroll
                for (int tp = 0; tp < 16; tp++) {
                    ull q = qrow[tp];                 // one broadcast LDS -> two FFMA2
                    a0[tp] = ffma2(q, w0, a0[tp]);
                    a1[tp] = ffma2(q, w1, a1[tp]);
                }
            }
#pragma unroll
            for (int tp = 0; tp < 16; tp++) {
                float l0, h0, l1, h1;
                unpack2(a0[tp], l0, h0); unpack2(a1[tp], l1, h1);
                int t0 = base + 2 * tp;
                if (t0 < ntok)     *(float2*)(out + (size_t)t0 * DIMX + e0)       = make_float2(l0, l1);
                if (t0 + 1 < ntok) *(float2*)(out + (size_t)(t0 + 1) * DIMX + e0) = make_float2(h0, h1);
            }
        }

        // ---- entropy / index / commit: warp 0, lane = token ----
        if (wid == 0) {
            int t = base + lane;
            float E = 0.0f, commit = 0.0f, lpmax = 0.0f;
            int idx = 0, k = 0;
            float wts[CBD]; int msk[CBD];
            if (t < ntok) {
#pragma unroll
                for (int d = 0; d < CBD; d++) {
                    float hv = shh[d * 32 + lane];
                    float a = fabsf(hv);
                    if (hv > 0.0f) idx |= 1 << (13 - d);
                    float dm = a - 1.0f;
                    commit += dm * dm;
                    float e4 = 400.0f * a;
                    if (e4 < 40.0f) { lpmax -= log1pf(__expf(-e4)); wts[k] = e4; msk[k] = 1 << (13 - d); k++; }
                }
                const float LCLIP = -11.512925465f;   // log(1e-5)
                const int M = 1 << k;
                for (int m = 0; m < M; m++) {
                    float lp = lpmax; int flip = 0;
                    for (int i = 0; i < k; i++)
                        if ((m >> i) & 1) { lp -= wts[i]; flip |= msk[i]; }
                    float p = __expf(lp);
                    E -= p * fmaxf(lp, LCLIP);
                    atomicAdd(&g_avgp[idx ^ flip], p);
                }
                idxf[t] = (float)idx;
            }
#pragma unroll
            for (int o = 16; o; o >>= 1) {
                E      += __shfl_xor_sync(0xffffffffu, E, o);
                commit += __shfl_xor_sync(0xffffffffu, commit, o);
            }
            if (lane == 0) { atomicAdd(&g_scal[0], E); atomicAdd(&g_scal[1], commit); }
        }
    }

    // ================= in-kernel final reduction (no 2nd launch) =================
    // All gridDim.x blocks are co-resident (1 block/SM) -> spin-sync is safe.
    __syncthreads();
    __threadfence();
    if (tid == 0) {
        atomicAdd(&g_ctr, 1u);
        unsigned v;
        do {
            asm volatile("ld.acquire.gpu.u32 %0, [%1];" : "=r"(v) : "l"(&g_ctr) : "memory");
        } while (v < (unsigned)gridDim.x);
    }
    __syncthreads();

    // each block reduces its slice of g_avgp (CBS/gridDim.x bins)
    const float inv_n = 1.0f / (float)ntok;
    const int slice = CBS / gridDim.x;           // 128 for grid=128
    const int jbeg = blockIdx.x * slice;
    float s = 0.0f;
    for (int j = jbeg + tid; j < jbeg + slice; j += NTHR) {
        float v = g_avgp[j];
        g_avgp[j] = 0.0f;                        // reset for next graph replay
        float a = v * inv_n;
        s -= a * logf(fmaxf(a, 1e-5f));          // a==0 contributes exactly 0
    }
#pragma unroll
    for (int o = 16; o; o >>= 1) s += __shfl_xor_sync(0xffffffffu, s, o);
    {
        __shared__ float red[8];
        if (lane == 0) red[wid] = s;
        __syncthreads();
        if (tid == 0) {
            float bs = red[0];
#pragma unroll
            for (int w = 1; w < 8; w++) bs += red[w];
            atomicAdd(&g_ent, bs);
            __threadfence();
            unsigned old = atomicAdd(&g_ctr2, 1u);
            if (old == (unsigned)(gridDim.x - 1)) {
                float cbent;
                asm volatile("ld.acquire.gpu.f32 %0, [%1];" : "=f"(cbent) : "l"(&g_ent) : "memory");
                float ps = g_scal[0] * inv_n;
                float cm = g_scal[1] * (inv_n / (float)CBD);
                aux[0] = 0.1f * (ps - cbent) + 0.25f * cm;
                // reset persistent state for next replay
                g_ent = 0.0f; g_ctr = 0u; g_ctr2 = 0u;
                g_scal[0] = 0.0f; g_scal[1] = 0.0f;
            }
        }
    }
}

extern "C" void kernel_launch(void* const* d_in, const int* in_sizes, int n_in,
                              void* d_out, int out_size)
{
    const float* x     = (const float*)d_in[0];
    const float* w_in  = (const float*)d_in[1];
    const float* b_in  = (const float*)d_in[2];
    const float* w_out = (const float*)d_in[3];
    const float* b_out = (const float*)d_in[4];

    const int ntok = in_sizes[0] / DIMX;   // 4096

    float* out  = (float*)d_out;
    float* idxf = out + (size_t)ntok * DIMX;
    float* aux  = idxf + ntok;

    cudaFuncSetAttribute(lfq_main, cudaFuncAttributeMaxDynamicSharedMemorySize, SMEM_TOTAL);

    int nblk = (ntok + TPB - 1) / TPB;
    if (nblk > MAXBLK) nblk = MAXBLK;
    lfq_main<<<nblk, NTHR, SMEM_TOTAL>>>(x, w_in, b_in, w_out, b_out, out, idxf, aux, ntok);
}